// round 2
// baseline (speedup 1.0000x reference)
#include <cuda_runtime.h>
#include <cstdint>

// ---------------------------------------------------------------------------
// WaveBNN: 4 binary conv branches -> 1440-bit concat -> binary FC1(64) -> FC2(5)
// Strategy: fold BN into conv taps, pack pooled sign bits (16 bits/group,
// 90 groups = 45 u32 words), FC1 via XOR+popcount, FC2 as +/- accumulation.
// ---------------------------------------------------------------------------

#define NBR 4
#define OUTCH 16
#define NWORDS 45
#define NWPAD 48          // padded to 48 words (16B multiples) for uint4 loads
#define FC1N 64
#define FC2N 5
#define TPB 128

// scratch (device globals; no allocation allowed)
__device__ uint32_t d_wbits[FC1N * NWPAD];        // packed sign(fc1_w), our bit order
__device__ float    d_convW[NBR * OUTCH * 3];     // sign(w)*A folded taps
__device__ float    d_convB[NBR * OUTCH];         // beta - mean*A
__device__ float    d_A1[FC1N], d_B1[FC1N];       // fc1 BN fold

// ---------------------------------------------------------------------------
// prep kernel 1: fold conv BN constants + fc1 BN constants
// ---------------------------------------------------------------------------
__global__ void prep_consts(
    const float* w0, const float* g0, const float* b0, const float* m0, const float* v0,
    const float* w1, const float* g1b, const float* b1b, const float* m1b, const float* v1b,
    const float* w2, const float* g2, const float* b2, const float* m2, const float* v2,
    const float* w3, const float* g3, const float* b3, const float* m3, const float* v3,
    const float* g1, const float* b1, const float* m1, const float* v1)
{
    int tid = threadIdx.x;
    if (tid < 64) {
        int br = tid >> 4, c = tid & 15;
        const float* ws[4] = {w0, w1, w2, w3};
        const float* gs[4] = {g0, g1b, g2, g3};
        const float* bs[4] = {b0, b1b, b2, b3};
        const float* ms[4] = {m0, m1b, m2, m3};
        const float* vs[4] = {v0, v1b, v2, v3};
        double A = (double)gs[br][c] * rsqrt((double)vs[br][c] + 1e-5);
        float Af = (float)A;
        d_convB[br * OUTCH + c] = (float)((double)bs[br][c] - (double)ms[br][c] * A);
        #pragma unroll
        for (int k = 0; k < 3; k++) {
            float wv = ws[br][c * 3 + k];
            float s = (wv > 0.f) ? 1.f : ((wv < 0.f) ? -1.f : 0.f);
            d_convW[(br * OUTCH + c) * 3 + k] = s * Af;
        }
    } else if (tid < 128) {
        int j = tid - 64;
        double A = (double)g1[j] * rsqrt((double)v1[j] + 1e-5);
        d_A1[j] = (float)A;
        d_B1[j] = (float)((double)b1[j] - (double)m1[j] * A);
    }
}

// ---------------------------------------------------------------------------
// prep kernel 2: repack sign(fc1_w) into our bit order.
// our bit index: gbit = (GOFF[branch] + pooled_t)*16 + channel
// reference concat column: OFF[branch] + channel*LP[branch] + pooled_t
// ---------------------------------------------------------------------------
__global__ void prep_wbits(const float* fc1w)
{
    int gid = blockIdx.x * blockDim.x + threadIdx.x;
    if (gid >= FC1N * NWPAD) return;
    int j = gid / NWPAD, wi = gid % NWPAD;
    const int OFF[4] = {0, 176, 352, 704};
    const int LPa[4] = {11, 11, 22, 46};
    uint32_t wrd = 0;
    #pragma unroll 4
    for (int i = 0; i < 32; i++) {
        int gb = wi * 32 + i;
        if (gb < 1440) {
            int grp = gb >> 4, c = gb & 15, br, t;
            if (grp < 11)      { br = 0; t = grp; }
            else if (grp < 22) { br = 1; t = grp - 11; }
            else if (grp < 44) { br = 2; t = grp - 22; }
            else               { br = 3; t = grp - 44; }
            int col = OFF[br] + c * LPa[br] + t;
            if (fc1w[j * 1440 + col] > 0.f) wrd |= (1u << i);
        }
    }
    d_wbits[gid] = wrd;
}

// ---------------------------------------------------------------------------
// main kernel: one thread per row
// ---------------------------------------------------------------------------
template<int L, int LP, int BR, int GBASE>
__device__ __forceinline__ void run_branch(
    const float* __restrict__ x, int row,
    const float (&s_cw)[NBR][OUTCH][3], const float (&s_cb)[NBR][OUTCH],
    uint32_t* __restrict__ mybits, uint32_t& acc)
{
    float W[OUTCH][3], Bc[OUTCH];
    #pragma unroll
    for (int c = 0; c < OUTCH; c++) {
        W[c][0] = s_cw[BR][c][0];
        W[c][1] = s_cw[BR][c][1];
        W[c][2] = s_cw[BR][c][2];
        Bc[c]   = s_cb[BR][c];
    }
    const float* xr = x + (size_t)row * L;
    float xa = xr[0], xb = xr[1];
    #pragma unroll 2
    for (int t = 0; t < LP; t++) {
        float xc = xr[2 * t + 2];
        float xd = xr[2 * t + 3];
        uint32_t mask = 0;
        #pragma unroll
        for (int c = 0; c < OUTCH; c++) {
            float y0 = fmaf(xa, W[c][0], fmaf(xb, W[c][1], fmaf(xc, W[c][2], Bc[c])));
            float y1 = fmaf(xb, W[c][0], fmaf(xc, W[c][1], fmaf(xd, W[c][2], Bc[c])));
            if (fmaxf(y0, y1) > 0.0f) mask |= (1u << c);
        }
        int g = GBASE + t;
        if (g & 1) mybits[g >> 1] = acc | (mask << 16);
        else       acc = mask;
        xa = xc; xb = xd;
    }
}

__global__ void __launch_bounds__(TPB)
wavebnn_main(const float* __restrict__ xA,  const float* __restrict__ xD3,
             const float* __restrict__ xD2, const float* __restrict__ xD1,
             const float* __restrict__ fc2w, const float* __restrict__ fc2b,
             float* __restrict__ out, int rows)
{
    __shared__ __align__(16) uint32_t s_wb[FC1N * NWPAD];   // 12 KB
    __shared__ float s_cw[NBR][OUTCH][3];
    __shared__ float s_cb[NBR][OUTCH];
    __shared__ float s_A1[FC1N], s_B1[FC1N];
    __shared__ float s_w2[FC2N * FC1N];
    __shared__ float s_b2[8];
    __shared__ uint32_t s_bits[TPB * 49];                   // stride 49: conflict-free

    int tid = threadIdx.x;

    // cooperative load of all constants
    for (int i = tid; i < FC1N * NWPAD; i += TPB) s_wb[i] = d_wbits[i];
    for (int i = tid; i < NBR * OUTCH * 3; i += TPB) (&s_cw[0][0][0])[i] = d_convW[i];
    for (int i = tid; i < NBR * OUTCH; i += TPB)     (&s_cb[0][0])[i]    = d_convB[i];
    for (int i = tid; i < FC1N; i += TPB) { s_A1[i] = d_A1[i]; s_B1[i] = d_B1[i]; }
    for (int i = tid; i < FC2N * FC1N; i += TPB) s_w2[i] = fc2w[i];
    if (tid < FC2N) s_b2[tid] = fc2b[tid];
    __syncthreads();

    int row = blockIdx.x * TPB + tid;
    if (row >= rows) return;

    uint32_t* mybits = &s_bits[tid * 49];
    uint32_t acc = 0;

    // four branches: group bases 0, 11, 22, 44 (90 groups -> 45 words, all written)
    run_branch<24, 11, 0, 0 >(xA,  row, s_cw, s_cb, mybits, acc);
    run_branch<24, 11, 1, 11>(xD3, row, s_cw, s_cb, mybits, acc);
    run_branch<47, 22, 2, 22>(xD2, row, s_cw, s_cb, mybits, acc);
    run_branch<94, 46, 3, 44>(xD1, row, s_cw, s_cb, mybits, acc);

    // pull own bits into registers (within-thread smem ordering: no sync needed)
    uint32_t a[NWPAD];
    #pragma unroll
    for (int w = 0; w < NWORDS; w++) a[w] = mybits[w];
    a[45] = 0; a[46] = 0; a[47] = 0;

    float o0 = s_b2[0], o1 = s_b2[1], o2 = s_b2[2], o3 = s_b2[3], o4 = s_b2[4];

    #pragma unroll 2
    for (int j = 0; j < FC1N; j++) {
        const uint32_t* wj = &s_wb[j * NWPAD];
        int s = 0;
        #pragma unroll
        for (int q = 0; q < NWPAD / 4; q++) {
            uint4 wv = *reinterpret_cast<const uint4*>(&wj[q * 4]);
            s += __popc(a[4 * q + 0] ^ wv.x) + __popc(a[4 * q + 1] ^ wv.y)
               + __popc(a[4 * q + 2] ^ wv.z) + __popc(a[4 * q + 3] ^ wv.w);
        }
        float d = (float)(1440 - 2 * s);               // exact integer dot
        float val = fmaf(d, s_A1[j], s_B1[j]);
        float sg = (val > 0.0f) ? 1.0f : -1.0f;
        o0 = fmaf(sg, s_w2[0 * FC1N + j], o0);
        o1 = fmaf(sg, s_w2[1 * FC1N + j], o1);
        o2 = fmaf(sg, s_w2[2 * FC1N + j], o2);
        o3 = fmaf(sg, s_w2[3 * FC1N + j], o3);
        o4 = fmaf(sg, s_w2[4 * FC1N + j], o4);
    }

    float* op = out + (size_t)row * FC2N;
    op[0] = o0; op[1] = o1; op[2] = o2; op[3] = o3; op[4] = o4;
}

// ---------------------------------------------------------------------------
// launch: detect input ordering from sizes.
//   Order A (interleaved, dict order): x_cA3,w,g,b,m,v, x_cD3,..., x_cD2,...,
//                                      x_cD1,..., fc1_w,g1,b1,m1,v1,fc2_w,fc2_b
//   Order B (signature order):         x_cA3,x_cD3,x_cD2,x_cD1, then params.
// ---------------------------------------------------------------------------
extern "C" void kernel_launch(void* const* d_in, const int* in_sizes, int n_in,
                              void* d_out, int out_size)
{
    const float *xA, *xD3, *xD2, *xD1;
    const float *wA,*gA,*bA,*mA,*vA, *wB,*gB,*bB,*mB,*vB;
    const float *wC,*gC,*bC,*mC,*vC, *wD,*gD,*bD,*mD,*vD;
    const float *fc1w,*g1,*b1,*m1,*v1,*fc2w,*fc2b;

    bool interleaved = (in_sizes[1] != in_sizes[0]);   // big x vs tiny w_cA3

    if (interleaved) {
        xA  = (const float*)d_in[0];
        wA  = (const float*)d_in[1];  gA = (const float*)d_in[2];
        bA  = (const float*)d_in[3];  mA = (const float*)d_in[4];  vA = (const float*)d_in[5];
        xD3 = (const float*)d_in[6];
        wB  = (const float*)d_in[7];  gB = (const float*)d_in[8];
        bB  = (const float*)d_in[9];  mB = (const float*)d_in[10]; vB = (const float*)d_in[11];
        xD2 = (const float*)d_in[12];
        wC  = (const float*)d_in[13]; gC = (const float*)d_in[14];
        bC  = (const float*)d_in[15]; mC = (const float*)d_in[16]; vC = (const float*)d_in[17];
        xD1 = (const float*)d_in[18];
        wD  = (const float*)d_in[19]; gD = (const float*)d_in[20];
        bD  = (const float*)d_in[21]; mD = (const float*)d_in[22]; vD = (const float*)d_in[23];
        fc1w = (const float*)d_in[24];
        g1 = (const float*)d_in[25]; b1 = (const float*)d_in[26];
        m1 = (const float*)d_in[27]; v1 = (const float*)d_in[28];
        fc2w = (const float*)d_in[29]; fc2b = (const float*)d_in[30];
    } else {
        xA  = (const float*)d_in[0];
        xD3 = (const float*)d_in[1];
        xD2 = (const float*)d_in[2];
        xD1 = (const float*)d_in[3];
        wA  = (const float*)d_in[4];  gA = (const float*)d_in[5];
        bA  = (const float*)d_in[6];  mA = (const float*)d_in[7];  vA = (const float*)d_in[8];
        wB  = (const float*)d_in[9];  gB = (const float*)d_in[10];
        bB  = (const float*)d_in[11]; mB = (const float*)d_in[12]; vB = (const float*)d_in[13];
        wC  = (const float*)d_in[14]; gC = (const float*)d_in[15];
        bC  = (const float*)d_in[16]; mC = (const float*)d_in[17]; vC = (const float*)d_in[18];
        wD  = (const float*)d_in[19]; gD = (const float*)d_in[20];
        bD  = (const float*)d_in[21]; mD = (const float*)d_in[22]; vD = (const float*)d_in[23];
        fc1w = (const float*)d_in[24];
        g1 = (const float*)d_in[25]; b1 = (const float*)d_in[26];
        m1 = (const float*)d_in[27]; v1 = (const float*)d_in[28];
        fc2w = (const float*)d_in[29]; fc2b = (const float*)d_in[30];
    }

    int rows = in_sizes[0] / 24;

    prep_consts<<<1, 128>>>(wA, gA, bA, mA, vA,
                            wB, gB, bB, mB, vB,
                            wC, gC, bC, mC, vC,
                            wD, gD, bD, mD, vD,
                            g1, b1, m1, v1);
    prep_wbits<<<(FC1N * NWPAD + 255) / 256, 256>>>(fc1w);
    wavebnn_main<<<(rows + TPB - 1) / TPB, TPB>>>(xA, xD3, xD2, xD1,
                                                  fc2w, fc2b, (float*)d_out, rows);
}

// round 3
// speedup vs baseline: 1.0845x; 1.0845x over previous
#include <cuda_runtime.h>
#include <cstdint>

// ---------------------------------------------------------------------------
// WaveBNN: 4 binary conv branches -> 1440-bit concat -> binary FC1(64) -> FC2(5)
// R3: coalesced smem staging of x (chunked), wbits via __ldg broadcast,
//     4 blocks/SM single-wave occupancy, merged prep kernel.
// ---------------------------------------------------------------------------

#define NBR 4
#define OUTCH 16
#define NWORDS 45
#define NWPAD 48
#define FC1N 64
#define FC2N 5
#define TPB 128
#define XSTRIDE 27          // odd: conflict-free conv reads (max chunk cols = 26)
#define BSTRIDE 47          // odd: conflict-free bit-word accesses

// scratch (device globals; no allocation allowed)
__device__ uint32_t d_wbits[FC1N * NWPAD];        // packed sign(fc1_w), our bit order
__device__ float    d_convW[NBR * OUTCH * 3];     // sign(w)*A folded taps
__device__ float    d_convB[NBR * OUTCH];         // beta - mean*A
__device__ float    d_A1[FC1N], d_B1[FC1N];       // fc1 BN fold

// ---------------------------------------------------------------------------
// merged prep kernel: blocks 0..11 pack fc1 weight bits, block 12 folds consts
// ---------------------------------------------------------------------------
__global__ void prep_all(
    const float* w0, const float* g0, const float* b0, const float* m0, const float* v0,
    const float* w1, const float* g1b, const float* b1b, const float* m1b, const float* v1b,
    const float* w2, const float* g2, const float* b2, const float* m2, const float* v2,
    const float* w3, const float* g3, const float* b3, const float* m3, const float* v3,
    const float* g1, const float* b1, const float* m1, const float* v1,
    const float* fc1w)
{
    int tid = threadIdx.x;
    if (blockIdx.x == 12) {
        if (tid < 64) {
            int br = tid >> 4, c = tid & 15;
            const float* ws[4] = {w0, w1, w2, w3};
            const float* gs[4] = {g0, g1b, g2, g3};
            const float* bs[4] = {b0, b1b, b2, b3};
            const float* ms[4] = {m0, m1b, m2, m3};
            const float* vs[4] = {v0, v1b, v2, v3};
            double A = (double)gs[br][c] * rsqrt((double)vs[br][c] + 1e-5);
            float Af = (float)A;
            d_convB[br * OUTCH + c] = (float)((double)bs[br][c] - (double)ms[br][c] * A);
            #pragma unroll
            for (int k = 0; k < 3; k++) {
                float wv = ws[br][c * 3 + k];
                float s = (wv > 0.f) ? 1.f : ((wv < 0.f) ? -1.f : 0.f);
                d_convW[(br * OUTCH + c) * 3 + k] = s * Af;
            }
        } else if (tid < 128) {
            int j = tid - 64;
            double A = (double)g1[j] * rsqrt((double)v1[j] + 1e-5);
            d_A1[j] = (float)A;
            d_B1[j] = (float)((double)b1[j] - (double)m1[j] * A);
        }
        return;
    }
    int gid = blockIdx.x * 256 + tid;
    if (gid >= FC1N * NWPAD) return;
    int j = gid / NWPAD, wi = gid % NWPAD;
    const int OFF[4] = {0, 176, 352, 704};
    const int LPa[4] = {11, 11, 22, 46};
    uint32_t wrd = 0;
    #pragma unroll 4
    for (int i = 0; i < 32; i++) {
        int gb = wi * 32 + i;
        if (gb < 1440) {
            int grp = gb >> 4, c = gb & 15, br, t;
            if (grp < 11)      { br = 0; t = grp; }
            else if (grp < 22) { br = 1; t = grp - 11; }
            else if (grp < 44) { br = 2; t = grp - 22; }
            else               { br = 3; t = grp - 44; }
            int col = OFF[br] + c * LPa[br] + t;
            if (fc1w[j * 1440 + col] > 0.f) wrd |= (1u << i);
        }
    }
    d_wbits[gid] = wrd;
}

// ---------------------------------------------------------------------------
// main kernel helpers
// ---------------------------------------------------------------------------

// coalesced stage of a [TPB rows x COLS cols] slab (pitch L) into s_x (stride 27)
template<int COLS, int L>
__device__ __forceinline__ void stage_chunk(
    float* __restrict__ s_x, const float* __restrict__ xg, int rowbase, int c0, int tid)
{
    #pragma unroll
    for (int i = tid; i < TPB * COLS; i += TPB) {
        int r = i / COLS;
        int c = i - r * COLS;
        s_x[r * XSTRIDE + c] = xg[(size_t)(rowbase + r) * L + c0 + c];
    }
}

// process NP pooled positions from staged chunk (local cols 0..2*NP+1)
template<int NP>
__device__ __forceinline__ void run_chunk(
    const float* __restrict__ sx,            // s_x + tid*XSTRIDE
    const float (&W)[OUTCH][3], const float (&Bc)[OUTCH],
    int gbase, uint32_t* __restrict__ mybits, uint32_t& acc)
{
    float xa = sx[0], xb = sx[1];
    #pragma unroll 2
    for (int t = 0; t < NP; t++) {
        float xc = sx[2 * t + 2];
        float xd = sx[2 * t + 3];
        uint32_t mask = 0;
        #pragma unroll
        for (int c = 0; c < OUTCH; c++) {
            float y0 = fmaf(xa, W[c][0], fmaf(xb, W[c][1], fmaf(xc, W[c][2], Bc[c])));
            float y1 = fmaf(xb, W[c][0], fmaf(xc, W[c][1], fmaf(xd, W[c][2], Bc[c])));
            if (fmaxf(y0, y1) > 0.0f) mask |= (1u << c);
        }
        int g = gbase + t;
        if (g & 1) mybits[(g >> 1) ] = acc | (mask << 16);
        else       acc = mask;
        xa = xc; xb = xd;
    }
}

__global__ void __launch_bounds__(TPB, 4)
wavebnn_main(const float* __restrict__ xA,  const float* __restrict__ xD3,
             const float* __restrict__ xD2, const float* __restrict__ xD1,
             const float* __restrict__ fc2w, const float* __restrict__ fc2b,
             float* __restrict__ out, int rows)
{
    __shared__ float    s_x[TPB * XSTRIDE];              // 13.8 KB staging
    __shared__ uint32_t s_bits[TPB * BSTRIDE];           // 24.1 KB bit words
    __shared__ float s_cw[NBR][OUTCH][3];
    __shared__ float s_cb[NBR][OUTCH];
    __shared__ float s_A1[FC1N], s_B1[FC1N];
    __shared__ float s_w2[FC2N * FC1N];
    __shared__ float s_b2[8];

    int tid = threadIdx.x;
    int rowbase = blockIdx.x * TPB;

    for (int i = tid; i < NBR * OUTCH * 3; i += TPB) (&s_cw[0][0][0])[i] = d_convW[i];
    for (int i = tid; i < NBR * OUTCH; i += TPB)     (&s_cb[0][0])[i]    = d_convB[i];
    for (int i = tid; i < FC1N; i += TPB) { s_A1[i] = d_A1[i]; s_B1[i] = d_B1[i]; }
    for (int i = tid; i < FC2N * FC1N; i += TPB) s_w2[i] = fc2w[i];
    if (tid < FC2N) s_b2[tid] = fc2b[tid];

    uint32_t* mybits = &s_bits[tid * BSTRIDE];
    const float* sx = &s_x[tid * XSTRIDE];
    uint32_t acc = 0;

    float W[OUTCH][3], Bc[OUTCH];

    // ---- branch A3 (L=24, LP=11, gbase 0) ----
    #pragma unroll
    for (int c = 0; c < OUTCH; c++) { W[c][0]=d_convW[(0*OUTCH+c)*3+0]; W[c][1]=d_convW[(0*OUTCH+c)*3+1]; W[c][2]=d_convW[(0*OUTCH+c)*3+2]; Bc[c]=d_convB[0*OUTCH+c]; }
    __syncthreads();
    stage_chunk<24, 24>(s_x, xA, rowbase, 0, tid);
    __syncthreads();
    run_chunk<11>(sx, W, Bc, 0, mybits, acc);

    // ---- branch D3 (L=24, LP=11, gbase 11) ----
    #pragma unroll
    for (int c = 0; c < OUTCH; c++) { W[c][0]=s_cw[1][c][0]; W[c][1]=s_cw[1][c][1]; W[c][2]=s_cw[1][c][2]; Bc[c]=s_cb[1][c]; }
    __syncthreads();
    stage_chunk<24, 24>(s_x, xD3, rowbase, 0, tid);
    __syncthreads();
    run_chunk<11>(sx, W, Bc, 11, mybits, acc);

    // ---- branch D2 (L=47, LP=22, gbase 22): chunks p0=0 (NP=11), p0=11 (NP=11) ----
    #pragma unroll
    for (int c = 0; c < OUTCH; c++) { W[c][0]=s_cw[2][c][0]; W[c][1]=s_cw[2][c][1]; W[c][2]=s_cw[2][c][2]; Bc[c]=s_cb[2][c]; }
    __syncthreads();
    stage_chunk<24, 47>(s_x, xD2, rowbase, 0, tid);
    __syncthreads();
    run_chunk<11>(sx, W, Bc, 22, mybits, acc);
    __syncthreads();
    stage_chunk<24, 47>(s_x, xD2, rowbase, 22, tid);
    __syncthreads();
    run_chunk<11>(sx, W, Bc, 33, mybits, acc);

    // ---- branch D1 (L=94, LP=46, gbase 44): chunks p0=0,12,24,35 (NP=12,12,11,11) ----
    #pragma unroll
    for (int c = 0; c < OUTCH; c++) { W[c][0]=s_cw[3][c][0]; W[c][1]=s_cw[3][c][1]; W[c][2]=s_cw[3][c][2]; Bc[c]=s_cb[3][c]; }
    __syncthreads();
    stage_chunk<26, 94>(s_x, xD1, rowbase, 0, tid);
    __syncthreads();
    run_chunk<12>(sx, W, Bc, 44, mybits, acc);
    __syncthreads();
    stage_chunk<26, 94>(s_x, xD1, rowbase, 24, tid);
    __syncthreads();
    run_chunk<12>(sx, W, Bc, 56, mybits, acc);
    __syncthreads();
    stage_chunk<24, 94>(s_x, xD1, rowbase, 48, tid);
    __syncthreads();
    run_chunk<11>(sx, W, Bc, 68, mybits, acc);
    __syncthreads();
    stage_chunk<24, 94>(s_x, xD1, rowbase, 70, tid);
    __syncthreads();
    run_chunk<11>(sx, W, Bc, 79, mybits, acc);

    // ---- FC1 (XOR/popcount vs __ldg-broadcast weight words) + BN + sign + FC2 ----
    uint32_t a[NWPAD];
    #pragma unroll
    for (int w = 0; w < NWORDS; w++) a[w] = mybits[w];
    a[45] = 0; a[46] = 0; a[47] = 0;

    float o0 = s_b2[0], o1 = s_b2[1], o2 = s_b2[2], o3 = s_b2[3], o4 = s_b2[4];

    #pragma unroll 2
    for (int j = 0; j < FC1N; j++) {
        const uint4* wj = reinterpret_cast<const uint4*>(&d_wbits[j * NWPAD]);
        int s = 0;
        #pragma unroll
        for (int q = 0; q < NWPAD / 4; q++) {
            uint4 wv = __ldg(&wj[q]);
            s += __popc(a[4 * q + 0] ^ wv.x) + __popc(a[4 * q + 1] ^ wv.y)
               + __popc(a[4 * q + 2] ^ wv.z) + __popc(a[4 * q + 3] ^ wv.w);
        }
        float d = (float)(1440 - 2 * s);               // exact integer dot
        float val = fmaf(d, s_A1[j], s_B1[j]);
        float sg = (val > 0.0f) ? 1.0f : -1.0f;
        o0 = fmaf(sg, s_w2[0 * FC1N + j], o0);
        o1 = fmaf(sg, s_w2[1 * FC1N + j], o1);
        o2 = fmaf(sg, s_w2[2 * FC1N + j], o2);
        o3 = fmaf(sg, s_w2[3 * FC1N + j], o3);
        o4 = fmaf(sg, s_w2[4 * FC1N + j], o4);
    }

    int row = rowbase + tid;
    if (row < rows) {
        float* op = out + (size_t)row * FC2N;
        op[0] = o0; op[1] = o1; op[2] = o2; op[3] = o3; op[4] = o4;
    }
}

// ---------------------------------------------------------------------------
// launch: detect input ordering from sizes (interleaved dict order vs grouped)
// ---------------------------------------------------------------------------
extern "C" void kernel_launch(void* const* d_in, const int* in_sizes, int n_in,
                              void* d_out, int out_size)
{
    const float *xA, *xD3, *xD2, *xD1;
    const float *wA,*gA,*bA,*mA,*vA, *wB,*gB,*bB,*mB,*vB;
    const float *wC,*gC,*bC,*mC,*vC, *wD,*gD,*bD,*mD,*vD;
    const float *fc1w,*g1,*b1,*m1,*v1,*fc2w,*fc2b;

    bool interleaved = (in_sizes[1] != in_sizes[0]);

    if (interleaved) {
        xA  = (const float*)d_in[0];
        wA  = (const float*)d_in[1];  gA = (const float*)d_in[2];
        bA  = (const float*)d_in[3];  mA = (const float*)d_in[4];  vA = (const float*)d_in[5];
        xD3 = (const float*)d_in[6];
        wB  = (const float*)d_in[7];  gB = (const float*)d_in[8];
        bB  = (const float*)d_in[9];  mB = (const float*)d_in[10]; vB = (const float*)d_in[11];
        xD2 = (const float*)d_in[12];
        wC  = (const float*)d_in[13]; gC = (const float*)d_in[14];
        bC  = (const float*)d_in[15]; mC = (const float*)d_in[16]; vC = (const float*)d_in[17];
        xD1 = (const float*)d_in[18];
        wD  = (const float*)d_in[19]; gD = (const float*)d_in[20];
        bD  = (const float*)d_in[21]; mD = (const float*)d_in[22]; vD = (const float*)d_in[23];
        fc1w = (const float*)d_in[24];
        g1 = (const float*)d_in[25]; b1 = (const float*)d_in[26];
        m1 = (const float*)d_in[27]; v1 = (const float*)d_in[28];
        fc2w = (const float*)d_in[29]; fc2b = (const float*)d_in[30];
    } else {
        xA  = (const float*)d_in[0];
        xD3 = (const float*)d_in[1];
        xD2 = (const float*)d_in[2];
        xD1 = (const float*)d_in[3];
        wA  = (const float*)d_in[4];  gA = (const float*)d_in[5];
        bA  = (const float*)d_in[6];  mA = (const float*)d_in[7];  vA = (const float*)d_in[8];
        wB  = (const float*)d_in[9];  gB = (const float*)d_in[10];
        bB  = (const float*)d_in[11]; mB = (const float*)d_in[12]; vB = (const float*)d_in[13];
        wC  = (const float*)d_in[14]; gC = (const float*)d_in[15];
        bC  = (const float*)d_in[16]; mC = (const float*)d_in[17]; vC = (const float*)d_in[18];
        wD  = (const float*)d_in[19]; gD = (const float*)d_in[20];
        bD  = (const float*)d_in[21]; mD = (const float*)d_in[22]; vD = (const float*)d_in[23];
        fc1w = (const float*)d_in[24];
        g1 = (const float*)d_in[25]; b1 = (const float*)d_in[26];
        m1 = (const float*)d_in[27]; v1 = (const float*)d_in[28];
        fc2w = (const float*)d_in[29]; fc2b = (const float*)d_in[30];
    }

    int rows = in_sizes[0] / 24;

    prep_all<<<13, 256>>>(wA, gA, bA, mA, vA,
                          wB, gB, bB, mB, vB,
                          wC, gC, bC, mC, vC,
                          wD, gD, bD, mD, vD,
                          g1, b1, m1, v1, fc1w);
    wavebnn_main<<<(rows + TPB - 1) / TPB, TPB>>>(xA, xD3, xD2, xD1,
                                                  fc2w, fc2b, (float*)d_out, rows);
}

// round 5
// speedup vs baseline: 1.1312x; 1.0430x over previous
#include <cuda_runtime.h>
#include <cstdint>

// ---------------------------------------------------------------------------
// WaveBNN R5: f32x2 dual-channel conv, cp.async double-buffered staging
// (dynamic smem), packed FC2. 90 pooled groups x 16ch -> 45 u32 words; FC1
// via XOR+POPC against __ldg-broadcast packed weights.
// ---------------------------------------------------------------------------

#define OUTCH 16
#define NWORDS 45
#define NWPAD 48
#define FC1N 64
#define FC2N 5
#define TPB 128
#define XST 25            // staging stride (odd -> conflict-free)
#define BST 45            // bits stride (odd -> conflict-free)
#define DYN_SMEM (2 * TPB * XST * 4 + TPB * BST * 4)   // 48640 bytes

// device scratch (no allocation allowed)
__device__ uint32_t           d_wbits[FC1N * NWPAD];
__device__ unsigned long long d_convWp[4 * 8 * 3];   // packed (W[2p],W[2p+1]) * A
__device__ unsigned long long d_convBp[4 * 8];       // packed folded bias pairs
__device__ float              d_A1[FC1N], d_B1[FC1N];

// ---------------- PTX helpers ----------------
__device__ __forceinline__ unsigned long long pk2(float lo, float hi) {
    unsigned long long d;
    asm("mov.b64 %0, {%1, %2};" : "=l"(d) : "f"(lo), "f"(hi));
    return d;
}
__device__ __forceinline__ void unpk2(unsigned long long v, float& lo, float& hi) {
    asm("mov.b64 {%0, %1}, %2;" : "=f"(lo), "=f"(hi) : "l"(v));
}
__device__ __forceinline__ unsigned long long ffma2(
    unsigned long long a, unsigned long long b, unsigned long long c) {
    unsigned long long d;
    asm("fma.rn.f32x2 %0, %1, %2, %3;" : "=l"(d) : "l"(a), "l"(b), "l"(c));
    return d;
}
__device__ __forceinline__ void cp_async4(uint32_t saddr, const float* gaddr) {
    asm volatile("cp.async.ca.shared.global [%0], [%1], 4;" :: "r"(saddr), "l"(gaddr));
}
#define CP_COMMIT() asm volatile("cp.async.commit_group;")
#define CP_WAIT1()  asm volatile("cp.async.wait_group 1;")
#define CP_WAIT0()  asm volatile("cp.async.wait_group 0;")

// ---------------------------------------------------------------------------
// prep: blocks 0..11 pack fc1 weight bits, block 12 folds BN constants
// ---------------------------------------------------------------------------
__global__ void prep_all(
    const float* w0, const float* g0, const float* b0, const float* m0, const float* v0,
    const float* w1, const float* g1b, const float* b1b, const float* m1b, const float* v1b,
    const float* w2, const float* g2, const float* b2, const float* m2, const float* v2,
    const float* w3, const float* g3, const float* b3, const float* m3, const float* v3,
    const float* g1, const float* b1, const float* m1, const float* v1,
    const float* fc1w)
{
    int tid = threadIdx.x;
    if (blockIdx.x == 12) {
        if (tid < 64) {
            int br = tid >> 4, c = tid & 15;
            int p = c >> 1, h = c & 1;
            const float* ws[4] = {w0, w1, w2, w3};
            const float* gs[4] = {g0, g1b, g2, g3};
            const float* bs[4] = {b0, b1b, b2, b3};
            const float* ms[4] = {m0, m1b, m2, m3};
            const float* vs[4] = {v0, v1b, v2, v3};
            double A = (double)gs[br][c] * rsqrt((double)vs[br][c] + 1e-5);
            float Af = (float)A;
            float* bp = (float*)d_convBp;
            bp[(br * 8 + p) * 2 + h] = (float)((double)bs[br][c] - (double)ms[br][c] * A);
            float* wp = (float*)d_convWp;
            #pragma unroll
            for (int k = 0; k < 3; k++) {
                float wv = ws[br][c * 3 + k];
                float s = (wv > 0.f) ? 1.f : ((wv < 0.f) ? -1.f : 0.f);
                wp[(((br * 8 + p) * 3) + k) * 2 + h] = s * Af;
            }
        } else if (tid < 128) {
            int j = tid - 64;
            double A = (double)g1[j] * rsqrt((double)v1[j] + 1e-5);
            d_A1[j] = (float)A;
            d_B1[j] = (float)((double)b1[j] - (double)m1[j] * A);
        }
        return;
    }
    int gid = blockIdx.x * 256 + tid;
    if (gid >= FC1N * NWPAD) return;
    int j = gid / NWPAD, wi = gid % NWPAD;
    const int OFF[4] = {0, 176, 352, 704};
    const int LPa[4] = {11, 11, 22, 46};
    uint32_t wrd = 0;
    #pragma unroll 4
    for (int i = 0; i < 32; i++) {
        int gb = wi * 32 + i;
        if (gb < 1440) {
            int grp = gb >> 4, c = gb & 15, br, t;
            if (grp < 11)      { br = 0; t = grp; }
            else if (grp < 22) { br = 1; t = grp - 11; }
            else if (grp < 44) { br = 2; t = grp - 22; }
            else               { br = 3; t = grp - 44; }
            int col = OFF[br] + c * LPa[br] + t;
            if (fc1w[j * 1440 + col] > 0.f) wrd |= (1u << i);
        }
    }
    d_wbits[gid] = wrd;
}

// ---------------------------------------------------------------------------
// main kernel device helpers
// ---------------------------------------------------------------------------
template<int COLS, int L>
__device__ __forceinline__ void stage_async(
    float* __restrict__ sdst, const float* __restrict__ xg,
    int rowbase, int c0, int tid)
{
    uint32_t sb = (uint32_t)__cvta_generic_to_shared(sdst);
    const float* gp = xg + (size_t)rowbase * L + c0;
    #pragma unroll
    for (int i = tid; i < TPB * COLS; i += TPB) {
        int r = i / COLS, c = i - r * COLS;
        cp_async4(sb + (uint32_t)(r * XST + c) * 4, gp + (size_t)r * L + c);
    }
}

template<int NP>
__device__ __forceinline__ void run_chunk(
    const float* __restrict__ sx,
    const unsigned long long (&Wp)[8][3], const unsigned long long (&Bp)[8],
    int gbase, uint32_t* __restrict__ mybits, uint32_t& acc)
{
    float xa = sx[0], xb = sx[1];
    unsigned long long dA = pk2(xa, xa), dB = pk2(xb, xb);
    #pragma unroll 2
    for (int t = 0; t < NP; t++) {
        float xc = sx[2 * t + 2];
        float xd = sx[2 * t + 3];
        unsigned long long dC = pk2(xc, xc), dD = pk2(xd, xd);
        uint32_t mask = 0;
        #pragma unroll
        for (int p = 0; p < 8; p++) {
            unsigned long long y0 = ffma2(dA, Wp[p][0],
                                    ffma2(dB, Wp[p][1],
                                    ffma2(dC, Wp[p][2], Bp[p])));
            unsigned long long y1 = ffma2(dB, Wp[p][0],
                                    ffma2(dC, Wp[p][1],
                                    ffma2(dD, Wp[p][2], Bp[p])));
            float a0, b0, a1, b1;
            unpk2(y0, a0, b0);
            unpk2(y1, a1, b1);
            if (a0 > 0.f || a1 > 0.f) mask |= (1u << (2 * p));
            if (b0 > 0.f || b1 > 0.f) mask |= (1u << (2 * p + 1));
        }
        int g = gbase + t;
        if (g & 1) mybits[g >> 1] = acc | (mask << 16);
        else       acc = mask;
        dA = dC; dB = dD;
    }
}

__device__ __forceinline__ void load_branch(
    const unsigned long long* __restrict__ s_cwp,
    const unsigned long long* __restrict__ s_cbp,
    int br, unsigned long long (&Wp)[8][3], unsigned long long (&Bp)[8])
{
    #pragma unroll
    for (int p = 0; p < 8; p++) {
        Wp[p][0] = s_cwp[(br * 8 + p) * 3 + 0];
        Wp[p][1] = s_cwp[(br * 8 + p) * 3 + 1];
        Wp[p][2] = s_cwp[(br * 8 + p) * 3 + 2];
        Bp[p]    = s_cbp[br * 8 + p];
    }
}

// ---------------------------------------------------------------------------
// main kernel (big buffers in dynamic smem: 48640 B)
// ---------------------------------------------------------------------------
__global__ void __launch_bounds__(TPB, 4)
wavebnn_main(const float* __restrict__ xA,  const float* __restrict__ xD3,
             const float* __restrict__ xD2, const float* __restrict__ xD1,
             const float* __restrict__ fc2w, const float* __restrict__ fc2b,
             float* __restrict__ out, int rows)
{
    extern __shared__ __align__(16) char dynsmem[];
    float*    s_xa   = (float*)dynsmem;                          // [TPB*XST]
    float*    s_xb   = (float*)(dynsmem + TPB * XST * 4);        // [TPB*XST]
    uint32_t* s_bits = (uint32_t*)(dynsmem + 2 * TPB * XST * 4); // [TPB*BST]

    __shared__ unsigned long long s_cwp[96], s_cbp[32];
    __shared__ float s_A1[FC1N], s_B1[FC1N];
    __shared__ __align__(16) float s_w2t[FC1N * 8];              // transposed fc2
    __shared__ float s_b2[8];

    int tid = threadIdx.x;
    int rowbase = blockIdx.x * TPB;

    // cooperative constant loads (completed by first __syncthreads below)
    if (tid < 96) s_cwp[tid] = d_convWp[tid];
    if (tid < 32) s_cbp[tid] = d_convBp[tid];
    if (tid < FC1N) { s_A1[tid] = d_A1[tid]; s_B1[tid] = d_B1[tid]; }
    #pragma unroll
    for (int idx = tid; idx < FC1N * 8; idx += TPB) {
        int j = idx >> 3, i = idx & 7;
        s_w2t[idx] = (i < FC2N) ? fc2w[i * FC1N + j] : 0.f;
    }
    if (tid < FC2N) s_b2[tid] = fc2b[tid];

    // pipeline prologue: chunks 0 and 1 in flight
    stage_async<24, 24>(s_xa, xA,  rowbase, 0, tid); CP_COMMIT();
    stage_async<24, 24>(s_xb, xD3, rowbase, 0, tid); CP_COMMIT();

    uint32_t* mybits = &s_bits[tid * BST];
    const float* sx0 = &s_xa[tid * XST];
    const float* sx1 = &s_xb[tid * XST];
    uint32_t acc = 0;

    unsigned long long Wp[8][3], Bp[8];

    // chunk sequence: buffers alternate a/b; group bases 0,11,22,33,44,...,88
    // ---- chunk 0 (A3) ----
    CP_WAIT1(); __syncthreads();
    load_branch(s_cwp, s_cbp, 0, Wp, Bp);
    run_chunk<11>(sx0, Wp, Bp, 0, mybits, acc);
    __syncthreads();
    stage_async<24, 47>(s_xa, xD2, rowbase, 0, tid); CP_COMMIT();   // chunk 2

    // ---- chunk 1 (D3) ----
    CP_WAIT1(); __syncthreads();
    load_branch(s_cwp, s_cbp, 1, Wp, Bp);
    run_chunk<11>(sx1, Wp, Bp, 11, mybits, acc);
    __syncthreads();
    stage_async<24, 47>(s_xb, xD2, rowbase, 22, tid); CP_COMMIT();  // chunk 3

    // ---- chunk 2 (D2 c0=0) ----
    CP_WAIT1(); __syncthreads();
    load_branch(s_cwp, s_cbp, 2, Wp, Bp);
    run_chunk<11>(sx0, Wp, Bp, 22, mybits, acc);
    __syncthreads();
    stage_async<24, 94>(s_xa, xD1, rowbase, 0, tid); CP_COMMIT();   // chunk 4

    // ---- chunk 3 (D2 c0=22) ----
    CP_WAIT1(); __syncthreads();
    run_chunk<11>(sx1, Wp, Bp, 33, mybits, acc);
    __syncthreads();
    stage_async<24, 94>(s_xb, xD1, rowbase, 22, tid); CP_COMMIT();  // chunk 5

    // ---- chunk 4 (D1 c0=0) ----
    CP_WAIT1(); __syncthreads();
    load_branch(s_cwp, s_cbp, 3, Wp, Bp);
    run_chunk<11>(sx0, Wp, Bp, 44, mybits, acc);
    __syncthreads();
    stage_async<24, 94>(s_xa, xD1, rowbase, 44, tid); CP_COMMIT();  // chunk 6

    // ---- chunk 5 (D1 c0=22) ----
    CP_WAIT1(); __syncthreads();
    run_chunk<11>(sx1, Wp, Bp, 55, mybits, acc);
    __syncthreads();
    stage_async<24, 94>(s_xb, xD1, rowbase, 66, tid); CP_COMMIT();  // chunk 7

    // ---- chunk 6 (D1 c0=44) ----
    CP_WAIT1(); __syncthreads();
    run_chunk<11>(sx0, Wp, Bp, 66, mybits, acc);
    __syncthreads();
    stage_async<6, 94>(s_xa, xD1, rowbase, 88, tid); CP_COMMIT();   // chunk 8

    // ---- chunk 7 (D1 c0=66) ----
    CP_WAIT1(); __syncthreads();
    run_chunk<11>(sx1, Wp, Bp, 77, mybits, acc);
    __syncthreads();

    // ---- chunk 8 (D1 c0=88, final 2 groups): newest group is OURS -> wait 0
    CP_WAIT0(); __syncthreads();
    run_chunk<2>(sx0, Wp, Bp, 88, mybits, acc);
    // g89 odd -> word 44 written; all 45 words complete

    // ---- FC1 (XOR/popcount vs __ldg weight words) + BN + sign + packed FC2 ----
    uint32_t a[NWPAD];
    #pragma unroll
    for (int w = 0; w < NWORDS; w++) a[w] = mybits[w];
    a[45] = 0; a[46] = 0; a[47] = 0;

    unsigned long long o01 = pk2(s_b2[0], s_b2[1]);
    unsigned long long o23 = pk2(s_b2[2], s_b2[3]);
    float o4 = s_b2[4];

    #pragma unroll 2
    for (int j = 0; j < FC1N; j++) {
        const uint4* wj = reinterpret_cast<const uint4*>(&d_wbits[j * NWPAD]);
        int s = 0;
        #pragma unroll
        for (int q = 0; q < NWPAD / 4; q++) {
            uint4 wv = __ldg(&wj[q]);
            s += __popc(a[4 * q + 0] ^ wv.x) + __popc(a[4 * q + 1] ^ wv.y)
               + __popc(a[4 * q + 2] ^ wv.z) + __popc(a[4 * q + 3] ^ wv.w);
        }
        float d = (float)(1440 - 2 * s);               // exact integer dot
        float val = fmaf(d, s_A1[j], s_B1[j]);
        float sg = (val > 0.0f) ? 1.0f : -1.0f;
        unsigned long long sgd = pk2(sg, sg);
        const unsigned long long* w2p =
            reinterpret_cast<const unsigned long long*>(&s_w2t[j * 8]);
        o01 = ffma2(sgd, w2p[0], o01);
        o23 = ffma2(sgd, w2p[1], o23);
        o4  = fmaf(sg, s_w2t[j * 8 + 4], o4);
    }

    int row = rowbase + tid;
    if (row < rows) {
        float r0, r1, r2, r3;
        unpk2(o01, r0, r1);
        unpk2(o23, r2, r3);
        float* op = out + (size_t)row * FC2N;
        op[0] = r0; op[1] = r1; op[2] = r2; op[3] = r3; op[4] = o4;
    }
}

// ---------------------------------------------------------------------------
// launch: detect input ordering from sizes (interleaved dict order vs grouped)
// ---------------------------------------------------------------------------
extern "C" void kernel_launch(void* const* d_in, const int* in_sizes, int n_in,
                              void* d_out, int out_size)
{
    const float *xA, *xD3, *xD2, *xD1;
    const float *wA,*gA,*bA,*mA,*vA, *wB,*gB,*bB,*mB,*vB;
    const float *wC,*gC,*bC,*mC,*vC, *wD,*gD,*bD,*mD,*vD;
    const float *fc1w,*g1,*b1,*m1,*v1,*fc2w,*fc2b;

    bool interleaved = (in_sizes[1] != in_sizes[0]);

    if (interleaved) {
        xA  = (const float*)d_in[0];
        wA  = (const float*)d_in[1];  gA = (const float*)d_in[2];
        bA  = (const float*)d_in[3];  mA = (const float*)d_in[4];  vA = (const float*)d_in[5];
        xD3 = (const float*)d_in[6];
        wB  = (const float*)d_in[7];  gB = (const float*)d_in[8];
        bB  = (const float*)d_in[9];  mB = (const float*)d_in[10]; vB = (const float*)d_in[11];
        xD2 = (const float*)d_in[12];
        wC  = (const float*)d_in[13]; gC = (const float*)d_in[14];
        bC  = (const float*)d_in[15]; mC = (const float*)d_in[16]; vC = (const float*)d_in[17];
        xD1 = (const float*)d_in[18];
        wD  = (const float*)d_in[19]; gD = (const float*)d_in[20];
        bD  = (const float*)d_in[21]; mD = (const float*)d_in[22]; vD = (const float*)d_in[23];
        fc1w = (const float*)d_in[24];
        g1 = (const float*)d_in[25]; b1 = (const float*)d_in[26];
        m1 = (const float*)d_in[27]; v1 = (const float*)d_in[28];
        fc2w = (const float*)d_in[29]; fc2b = (const float*)d_in[30];
    } else {
        xA  = (const float*)d_in[0];
        xD3 = (const float*)d_in[1];
        xD2 = (const float*)d_in[2];
        xD1 = (const float*)d_in[3];
        wA  = (const float*)d_in[4];  gA = (const float*)d_in[5];
        bA  = (const float*)d_in[6];  mA = (const float*)d_in[7];  vA = (const float*)d_in[8];
        wB  = (const float*)d_in[9];  gB = (const float*)d_in[10];
        bB  = (const float*)d_in[11]; mB = (const float*)d_in[12]; vB = (const float*)d_in[13];
        wC  = (const float*)d_in[14]; gC = (const float*)d_in[15];
        bC  = (const float*)d_in[16]; mC = (const float*)d_in[17]; vC = (const float*)d_in[18];
        wD  = (const float*)d_in[19]; gD = (const float*)d_in[20];
        bD  = (const float*)d_in[21]; mD = (const float*)d_in[22]; vD = (const float*)d_in[23];
        fc1w = (const float*)d_in[24];
        g1 = (const float*)d_in[25]; b1 = (const float*)d_in[26];
        m1 = (const float*)d_in[27]; v1 = (const float*)d_in[28];
        fc2w = (const float*)d_in[29]; fc2b = (const float*)d_in[30];
    }

    int rows = in_sizes[0] / 24;

    cudaFuncSetAttribute(wavebnn_main,
                         cudaFuncAttributeMaxDynamicSharedMemorySize, DYN_SMEM);

    prep_all<<<13, 256>>>(wA, gA, bA, mA, vA,
                          wB, gB, bB, mB, vB,
                          wC, gC, bC, mC, vC,
                          wD, gD, bD, mD, vD,
                          g1, b1, m1, v1, fc1w);
    wavebnn_main<<<(rows + TPB - 1) / TPB, TPB, DYN_SMEM>>>(
        xA, xD3, xD2, xD1, fc2w, fc2b, (float*)d_out, rows);
}